// round 10
// baseline (speedup 1.0000x reference)
#include <cuda_runtime.h>
#include <math.h>

#define SQ 4096
#define DMODEL 1024
#define NH 16
#define DH 64

typedef unsigned long long ull;

// Scratch (allocation-free rule: __device__ globals)
__device__ float g_q[SQ * DMODEL];
__device__ float g_k[SQ * DMODEL];
__device__ float g_v[SQ * DMODEL];
__device__ float g_attn[SQ * DMODEL];

// ---------------------------------------------------------------------------
// Packed fp32x2 helpers ("l" = b64 integer carrier)
// ---------------------------------------------------------------------------
__device__ __forceinline__ ull ffma2(ull a, ull b, ull c) {
    ull r;
    asm("fma.rn.f32x2 %0, %1, %2, %3;" : "=l"(r) : "l"(a), "l"(b), "l"(c));
    return r;
}
__device__ __forceinline__ ull pack2(float x) {
    ull r;
    asm("mov.b64 %0, {%1, %1};" : "=l"(r) : "f"(x));
    return r;
}
__device__ __forceinline__ void unpack2(ull d, float& lo, float& hi) {
    asm("mov.b64 {%0, %1}, %2;" : "=f"(lo), "=f"(hi) : "l"(d));
}

// tf32 helpers for the attention filter
__device__ __forceinline__ unsigned f2tf(float f) {
    unsigned u;
    asm("cvt.rna.tf32.f32 %0, %1;" : "=r"(u) : "f"(f));
    return u;
}
__device__ __forceinline__ void mma_tf32(
    float& c0, float& c1, float& c2, float& c3,
    unsigned a0, unsigned a1, unsigned a2, unsigned a3,
    unsigned b0, unsigned b1)
{
    asm volatile(
        "mma.sync.aligned.m16n8k8.row.col.f32.tf32.tf32.f32 "
        "{%0,%1,%2,%3}, {%4,%5,%6,%7}, {%8,%9}, {%0,%1,%2,%3};"
        : "+f"(c0), "+f"(c1), "+f"(c2), "+f"(c3)
        : "r"(a0), "r"(a1), "r"(a2), "r"(a3), "r"(b0), "r"(b1));
}

// ---------------------------------------------------------------------------
// K1: FUSED QKV SGEMM (R8/R9-verbatim, known good: 575us)
// ---------------------------------------------------------------------------
__global__ __launch_bounds__(256, 2) void sgemm_qkv(
    const float* __restrict__ A,
    const float* __restrict__ Wq, const float* __restrict__ Wk,
    const float* __restrict__ Wv,
    const float* __restrict__ bq, const float* __restrict__ bk,
    const float* __restrict__ bv,
    float* __restrict__ Cq, float* __restrict__ Ck, float* __restrict__ Cv)
{
    const int which = blockIdx.x >> 3;
    const float* __restrict__ B = (which == 0) ? Wq : (which == 1) ? Wk : Wv;
    const float* __restrict__ bias = (which == 0) ? bq : (which == 1) ? bk : bv;
    float* __restrict__ C = (which == 0) ? Cq : (which == 1) ? Ck : Cv;

    __shared__ float As[8][128];
    __shared__ float Bs[8][128];

    const int tid = threadIdx.x;
    const int tx = tid & 15, ty = tid >> 4;
    const int bx = (blockIdx.x & 7) * 128, by = blockIdx.y * 128;

    const int ar = tid >> 1;
    const int ac = (tid & 1) * 4;
    const int br = tid >> 5;
    const int bc = (tid & 31) * 4;

    ull acc2[8][4];
#pragma unroll
    for (int i = 0; i < 8; i++)
#pragma unroll
        for (int j = 0; j < 4; j++) acc2[i][j] = pack2(0.f);

    const float* Aptr = A + (size_t)(by + ar) * DMODEL + ac;
    const float* Bptr = B + (size_t)br * DMODEL + bx + bc;

    float4 av = *(const float4*)(Aptr);
    float4 bv4 = *(const float4*)(Bptr);

    for (int k0 = 0; k0 < DMODEL; k0 += 8) {
        As[ac + 0][ar] = av.x;
        As[ac + 1][ar] = av.y;
        As[ac + 2][ar] = av.z;
        As[ac + 3][ar] = av.w;
        *(float4*)&Bs[br][bc] = bv4;
        __syncthreads();

        if (k0 + 8 < DMODEL) {
            av = *(const float4*)(Aptr + k0 + 8);
            bv4 = *(const float4*)(Bptr + (size_t)(k0 + 8) * DMODEL);
        }

#pragma unroll
        for (int kk = 0; kk < 8; kk++) {
            ulonglong2 bA = *(const ulonglong2*)&Bs[kk][4 * tx];
            ulonglong2 bB = *(const ulonglong2*)&Bs[kk][64 + 4 * tx];
            float4 a0 = *(const float4*)&As[kk][ty * 8];
            float4 a1 = *(const float4*)&As[kk][ty * 8 + 4];
            float aa[8] = {a0.x, a0.y, a0.z, a0.w, a1.x, a1.y, a1.z, a1.w};
#pragma unroll
            for (int i = 0; i < 8; i++) {
                ull a2 = pack2(aa[i]);
                acc2[i][0] = ffma2(a2, bA.x, acc2[i][0]);
                acc2[i][1] = ffma2(a2, bA.y, acc2[i][1]);
                acc2[i][2] = ffma2(a2, bB.x, acc2[i][2]);
                acc2[i][3] = ffma2(a2, bB.y, acc2[i][3]);
            }
        }
        __syncthreads();
    }

    const int colA = bx + 4 * tx;
    const int colB = colA + 64;
    float4 biasA = *(const float4*)&bias[colA];
    float4 biasB = *(const float4*)&bias[colB];
#pragma unroll
    for (int i = 0; i < 8; i++) {
        int row = by + ty * 8 + i;
        float x0, x1, x2, x3;
        unpack2(acc2[i][0], x0, x1);
        unpack2(acc2[i][1], x2, x3);
        float4 oA = {x0 + biasA.x, x1 + biasA.y, x2 + biasA.z, x3 + biasA.w};
        unpack2(acc2[i][2], x0, x1);
        unpack2(acc2[i][3], x2, x3);
        float4 oB = {x0 + biasB.x, x1 + biasB.y, x2 + biasB.z, x3 + biasB.w};
        *(float4*)&C[(size_t)row * DMODEL + colA] = oA;
        *(float4*)&C[(size_t)row * DMODEL + colB] = oB;
    }
}

// ---------------------------------------------------------------------------
// K2: attention = tf32 TENSOR-CORE FILTER + EXACT FP32 RESCUE (R9 math),
// latency-restructured:
//   - DOUBLE-BUFFERED K tiles: LDG for tile n+1 issues at the start of each
//     t-loop half of tile n (latency hidden behind 8 MMA iterations; g_k is
//     L2-resident after the first head), cvt+STS after the half; ONE barrier
//     per tile instead of two.
//   - SPLIT MMA ACCUMULATOR CHAINS: s-even -> cA, s-odd -> cB, c = cA + cB
//     at the end. c is used only for min/threshold gating (rescue recomputes
//     exact scores), so this is semantics-preserving; chain depth 8 -> 4.
// All filter/rescue math is identical to R9 (rel_err 0.0).
// ---------------------------------------------------------------------------
#define MARGIN 0.5f
#define KBUF_FLOATS (16 * 32 * 20)               // 10240 floats = 40960 B
#define ATT_SMEM_BYTES (2 * KBUF_FLOATS * 4)     // 81920 B (Q staging fits in buf0)

__global__ __launch_bounds__(256, 2) void attn_kernel()
{
    extern __shared__ float smf[];

    const int tid = threadIdx.x;
    const int w = tid >> 5, lane = tid & 31;
    const int g = lane >> 2, t4 = lane & 3;
    const int q0 = blockIdx.x * 128;
    const int hb = blockIdx.y * DH;
    const int R0 = q0 + w * 16 + g;
    const int R1 = R0 + 8;
    const unsigned qmask = 0xFu << (lane & 28);

    // ---- Phase 1: stage Q (tf32) in buf0 area and extract A-fragments
    for (int it = 0; it < 8; it++) {
        int idx = tid + it * 256;
        int r = idx >> 4, d = (idx & 15) * 4;
        float4 t = *(const float4*)&g_q[(size_t)(q0 + r) * DMODEL + hb + d];
        smf[r * 68 + d + 0] = __uint_as_float(f2tf(t.x));
        smf[r * 68 + d + 1] = __uint_as_float(f2tf(t.y));
        smf[r * 68 + d + 2] = __uint_as_float(f2tf(t.z));
        smf[r * 68 + d + 3] = __uint_as_float(f2tf(t.w));
    }
    __syncthreads();
    unsigned afr[8][4];
    {
        const float* q0p = &smf[(w * 16 + g) * 68];
        const float* q1p = &smf[(w * 16 + g + 8) * 68];
#pragma unroll
        for (int s = 0; s < 8; s++) {
            afr[s][0] = __float_as_uint(q0p[8 * s + t4]);
            afr[s][1] = __float_as_uint(q1p[8 * s + t4]);
            afr[s][2] = __float_as_uint(q0p[8 * s + t4 + 4]);
            afr[s][3] = __float_as_uint(q1p[8 * s + t4 + 4]);
        }
    }
    __syncthreads();  // afr reads done before buf0 is overwritten

    // ---- Prologue: fill buf0 with K tile 0
    {
        for (int it = 0; it < 8; it++) {
            int idx = tid + it * 256;
            int r = idx >> 4, d = (idx & 15) * 4;
            float4 t = *(const float4*)&g_k[(size_t)(0 + r) * DMODEL + hb + d];
            int lb = (r >> 3) * 32 + (r & 7) * 4;
            int u = d >> 2;
            smf[(lb + 0) * 20 + u] = __uint_as_float(f2tf(t.x));
            smf[(lb + 1) * 20 + u] = __uint_as_float(f2tf(t.y));
            smf[(lb + 2) * 20 + u] = __uint_as_float(f2tf(t.z));
            smf[(lb + 3) * 20 + u] = __uint_as_float(f2tf(t.w));
        }
    }
    __syncthreads();

    float run0 = INFINITY, run1 = INFINITY;       // approx s-min (gating only)
    float rmax0 = -INFINITY, rmax1 = -INFINITY;   // exact-side state
    float rsum0 = 0.f, rsum1 = 0.f;
    float acc0[16], acc1[16];
#pragma unroll
    for (int d = 0; d < 16; d++) { acc0[d] = 0.f; acc1[d] = 0.f; }

    const int A0 = q0 + w * 16;
    const int ld_r = tid >> 4;              // fill row for (it batch): r = ld_r + it*... see below
    const int ld_d = (tid & 15) * 4;

    for (int k0 = 0; k0 < SQ; k0 += 128) {
        const int cur = (k0 >> 7) & 1;
        const int nxt = cur ^ 1;
        float* curb = smf + cur * KBUF_FLOATS;
        float* nxtb = smf + nxt * KBUF_FLOATS;
        const bool havenext = (k0 + 128) < SQ;
        const float* kn = &g_k[(size_t)(k0 + 128) * DMODEL + hb];

        const bool careful = (k0 <= A0 + 15) && (k0 + 127 >= A0 - 1);

        float4 pre[4];
        // ---- issue LDG batch A (rows 0..63 of next tile) before t-half 1
        if (havenext) {
#pragma unroll
            for (int it = 0; it < 4; it++)
                pre[it] = *(const float4*)&kn[(size_t)(ld_r + it * 16) * DMODEL + ld_d];
        }

#pragma unroll 1
        for (int t = 0; t < 8; t++) {
            const float* kf = &curb[(t * 32 + lane) * 20];
            float4 f0 = *(const float4*)&kf[0];
            float4 f1 = *(const float4*)&kf[4];
            float4 f2 = *(const float4*)&kf[8];
            float4 f3 = *(const float4*)&kf[12];
            unsigned br[16] = {
                __float_as_uint(f0.x), __float_as_uint(f0.y),
                __float_as_uint(f0.z), __float_as_uint(f0.w),
                __float_as_uint(f1.x), __float_as_uint(f1.y),
                __float_as_uint(f1.z), __float_as_uint(f1.w),
                __float_as_uint(f2.x), __float_as_uint(f2.y),
                __float_as_uint(f2.z), __float_as_uint(f2.w),
                __float_as_uint(f3.x), __float_as_uint(f3.y),
                __float_as_uint(f3.z), __float_as_uint(f3.w)};
            float cA0 = 0.f, cA1 = 0.f, cA2 = 0.f, cA3 = 0.f;
            float cB0 = 0.f, cB1 = 0.f, cB2 = 0.f, cB3 = 0.f;
#pragma unroll
            for (int s = 0; s < 8; s += 2) {
                mma_tf32(cA0, cA1, cA2, cA3,
                         afr[s][0], afr[s][1], afr[s][2], afr[s][3],
                         br[2 * s], br[2 * s + 1]);
                mma_tf32(cB0, cB1, cB2, cB3,
                         afr[s + 1][0], afr[s + 1][1], afr[s + 1][2], afr[s + 1][3],
                         br[2 * s + 2], br[2 * s + 3]);
            }
            float c0 = cA0 + cB0, c1 = cA1 + cB1;
            float c2 = cA2 + cB2, c3 = cA3 + cB3;

            const int j0 = k0 + 8 * t + 2 * t4;
            if (careful) {
                if (j0 == R0 || j0 == R0 - 1) c0 = INFINITY;
                if (j0 + 1 == R0 || j0 + 1 == R0 - 1) c1 = INFINITY;
                if (j0 == R1 || j0 == R1 - 1) c2 = INFINITY;
                if (j0 + 1 == R1 || j0 + 1 == R1 - 1) c3 = INFINITY;
            }
            float m0 = fminf(c0, c1), m1 = fminf(c2, c3);
            run0 = fminf(run0, m0);
            run1 = fminf(run1, m1);
            bool fl = (m0 <= run0 + MARGIN) || (m1 <= run1 + MARGIN);

            if (__any_sync(0xffffffffu, fl)) {
                unsigned bal[4];
                bal[0] = __ballot_sync(0xffffffffu, c0 <= run0 + MARGIN);
                bal[1] = __ballot_sync(0xffffffffu, c1 <= run0 + MARGIN);
                bal[2] = __ballot_sync(0xffffffffu, c2 <= run1 + MARGIN);
                bal[3] = __ballot_sync(0xffffffffu, c3 <= run1 + MARGIN);
#pragma unroll
                for (int e = 0; e < 4; e++) {
                    unsigned qb = (bal[e] >> (lane & 28)) & 0xFu;
                    const int i = (e >= 2) ? R1 : R0;
                    while (qb) {
                        int b = __ffs((int)qb) - 1;
                        qb &= qb - 1;
                        int j = k0 + 8 * t + 2 * b + (e & 1);
                        const float* qg = &g_q[(size_t)i * DMODEL + hb + t4 * 16];
                        const float* kg = &g_k[(size_t)j * DMODEL + hb + t4 * 16];
                        float s = 0.f;
#pragma unroll
                        for (int c4 = 0; c4 < 4; c4++) {
                            float4 qv = *(const float4*)&qg[c4 * 4];
                            float4 kv = *(const float4*)&kg[c4 * 4];
                            s = fmaf(qv.x, kv.x, s);
                            s = fmaf(qv.y, kv.y, s);
                            s = fmaf(qv.z, kv.z, s);
                            s = fmaf(qv.w, kv.w, s);
                        }
                        s += __shfl_xor_sync(qmask, s, 1);
                        s += __shfl_xor_sync(qmask, s, 2);
                        float y = s * 0.125f;
                        if (!(j == i || j == i - 1)) y = y * -1000000000.0f;
                        const float* vg = &g_v[(size_t)j * DMODEL + hb + t4 * 16];
                        if (e < 2) {
                            if (y > rmax0) {
                                float scl = expf(rmax0 - y);
                                rsum0 *= scl;
#pragma unroll
                                for (int d = 0; d < 16; d++) acc0[d] *= scl;
                                rmax0 = y;
                            }
                            float p = expf(y - rmax0);
                            rsum0 += p;
#pragma unroll
                            for (int c4 = 0; c4 < 4; c4++) {
                                float4 vv = *(const float4*)&vg[c4 * 4];
                                acc0[c4 * 4 + 0] = fmaf(p, vv.x, acc0[c4 * 4 + 0]);
                                acc0[c4 * 4 + 1] = fmaf(p, vv.y, acc0[c4 * 4 + 1]);
                                acc0[c4 * 4 + 2] = fmaf(p, vv.z, acc0[c4 * 4 + 2]);
                                acc0[c4 * 4 + 3] = fmaf(p, vv.w, acc0[c4 * 4 + 3]);
                            }
                        } else {
                            if (y > rmax1) {
                                float scl = expf(rmax1 - y);
                                rsum1 *= scl;
#pragma unroll
                                for (int d = 0; d < 16; d++) acc1[d] *= scl;
                                rmax1 = y;
                            }
                            float p = expf(y - rmax1);
                            rsum1 += p;
#pragma unroll
                            for (int c4 = 0; c4 < 4; c4++) {
                                float4 vv = *(const float4*)&vg[c4 * 4];
                                acc1[c4 * 4 + 0] = fmaf(p, vv.x, acc1[c4 * 4 + 0]);
                                acc1[c4 * 4 + 1] = fmaf(p, vv.y, acc1[c4 * 4 + 1]);
                                acc1[c4 * 4 + 2] = fmaf(p, vv.z, acc1[c4 * 4 + 2]);
                                acc1[c4 * 4 + 3] = fmaf(p, vv.w, acc1[c4 * 4 + 3]);
                            }
                        }
                    }
                }
            }
        }

        // ---- store batch A into nxt buffer; issue LDG batch B
        if (havenext) {
#pragma unroll
            for (int it = 0; it < 4; it++) {
                int r = ld_r + it * 16;
                int lb = (r >> 3) * 32 + (r & 7) * 4;
                int u = ld_d >> 2;
                nxtb[(lb + 0) * 20 + u] = __uint_as_float(f2tf(pre[it].x));
                nxtb[(lb + 1) * 20 + u] = __uint_as_float(f2tf(pre[it].y));
                nxtb[(lb + 2) * 20 + u] = __uint_as_float(f2tf(pre[it].z));
                nxtb[(lb + 3) * 20 + u] = __uint_as_float(f2tf(pre[it].w));
            }
#pragma unroll
            for (int it = 0; it < 4; it++)
                pre[it] = *(const float4*)&kn[(size_t)(ld_r + 64 + it * 16) * DMODEL + ld_d];
        }

#pragma unroll 1
        for (int t = 8; t < 16; t++) {
            const float* kf = &curb[(t * 32 + lane) * 20];
            float4 f0 = *(const float4*)&kf[0];
            float4 f1 = *(const float4*)&kf[4];
            float4 f2 = *(const float4*)&kf[8];
            float4 f3 = *(const float4*)&kf[12];
            unsigned br[16] = {
                __float_as_uint(f0.x), __float_as_uint(f0.y),
                __float_as_uint(f0.z), __float_as_uint(f0.w),
                __float_as_uint(f1.x), __float_as_uint(f1.y),
                __float_as_uint(f1.z), __float_as_uint(f1.w),
                __float_as_uint(f2.x), __float_as_uint(f2.y),
                __float_as_uint(f2.z), __float_as_uint(f2.w),
                __float_as_uint(f3.x), __float_as_uint(f3.y),
                __float_as_uint(f3.z), __float_as_uint(f3.w)};
            float cA0 = 0.f, cA1 = 0.f, cA2 = 0.f, cA3 = 0.f;
            float cB0 = 0.f, cB1 = 0.f, cB2 = 0.f, cB3 = 0.f;
#pragma unroll
            for (int s = 0; s < 8; s += 2) {
                mma_tf32(cA0, cA1, cA2, cA3,
                         afr[s][0], afr[s][1], afr[s][2], afr[s][3],
                         br[2 * s], br[2 * s + 1]);
                mma_tf32(cB0, cB1, cB2, cB3,
                         afr[s + 1][0], afr[s + 1][1], afr[s + 1][2], afr[s + 1][3],
                         br[2 * s + 2], br[2 * s + 3]);
            }
            float c0 = cA0 + cB0, c1 = cA1 + cB1;
            float c2 = cA2 + cB2, c3 = cA3 + cB3;

            const int j0 = k0 + 8 * t + 2 * t4;
            if (careful) {
                if (j0 == R0 || j0 == R0 - 1) c0 = INFINITY;
                if (j0 + 1 == R0 || j0 + 1 == R0 - 1) c1 = INFINITY;
                if (j0 == R1 || j0 == R1 - 1) c2 = INFINITY;
                if (j0 + 1 == R1 || j0 + 1 == R1 - 1) c3 = INFINITY;
            }
            float m0 = fminf(c0, c1), m1 = fminf(c2, c3);
            run0 = fminf(run0, m0);
            run1 = fminf(run1, m1);
            bool fl = (m0 <= run0 + MARGIN) || (m1 <= run1 + MARGIN);

            if (__any_sync(0xffffffffu, fl)) {
                unsigned bal[4];
                bal[0] = __ballot_sync(0xffffffffu, c0 <= run0 + MARGIN);
                bal[1] = __ballot_sync(0xffffffffu, c1 <= run0 + MARGIN);
                bal[2] = __ballot_sync(0xffffffffu, c2 <= run1 + MARGIN);
                bal[3] = __ballot_sync(0xffffffffu, c3 <= run1 + MARGIN);
#pragma unroll
                for (int e = 0; e < 4; e++) {
                    unsigned qb = (bal[e] >> (lane & 28)) & 0xFu;
                    const int i = (e >= 2) ? R1 : R0;
                    while (qb) {
                        int b = __ffs((int)qb) - 1;
                        qb &= qb - 1;
                        int j = k0 + 8 * t + 2 * b + (e & 1);
                        const float* qg = &g_q[(size_t)i * DMODEL + hb + t4 * 16];
                        const float* kg = &g_k[(size_t)j * DMODEL + hb + t4 * 16];
                        float s = 0.f;
#pragma unroll
                        for (int c4 = 0; c4 < 4; c4++) {
                            float4 qv = *(const float4*)&qg[c4 * 4];
                            float4 kv = *(const float4*)&kg[c4 * 4];
                            s = fmaf(qv.x, kv.x, s);
                            s = fmaf(qv.y, kv.y, s);
                            s = fmaf(qv.z, kv.z, s);
                            s = fmaf(qv.w, kv.w, s);
                        }
                        s += __shfl_xor_sync(qmask, s, 1);
                        s += __shfl_xor_sync(qmask, s, 2);
                        float y = s * 0.125f;
                        if (!(j == i || j == i - 1)) y = y * -1000000000.0f;
                        const float* vg = &g_v[(size_t)j * DMODEL + hb + t4 * 16];
                        if (e < 2) {
                            if (y > rmax0) {
                                float scl = expf(rmax0 - y);
                                rsum0 *= scl;
#pragma unroll
                                for (int d = 0; d < 16; d++) acc0[d] *= scl;
                                rmax0 = y;
                            }
                            float p = expf(y - rmax0);
                            rsum0 += p;
#pragma unroll
                            for (int c4 = 0; c4 < 4; c4++) {
                                float4 vv = *(const float4*)&vg[c4 * 4];
                                acc0[c4 * 4 + 0] = fmaf(p, vv.x, acc0[c4 * 4 + 0]);
                                acc0[c4 * 4 + 1] = fmaf(p, vv.y, acc0[c4 * 4 + 1]);
                                acc0[c4 * 4 + 2] = fmaf(p, vv.z, acc0[c4 * 4 + 2]);
                                acc0[c4 * 4 + 3] = fmaf(p, vv.w, acc0[c4 * 4 + 3]);
                            }
                        } else {
                            if (y > rmax1) {
                                float scl = expf(rmax1 - y);
                                rsum1 *= scl;
#pragma unroll
                                for (int d = 0; d < 16; d++) acc1[d] *= scl;
                                rmax1 = y;
                            }
                            float p = expf(y - rmax1);
                            rsum1 += p;
#pragma unroll
                            for (int c4 = 0; c4 < 4; c4++) {
                                float4 vv = *(const float4*)&vg[c4 * 4];
                                acc1[c4 * 4 + 0] = fmaf(p, vv.x, acc1[c4 * 4 + 0]);
                                acc1[c4 * 4 + 1] = fmaf(p, vv.y, acc1[c4 * 4 + 1]);
                                acc1[c4 * 4 + 2] = fmaf(p, vv.z, acc1[c4 * 4 + 2]);
                                acc1[c4 * 4 + 3] = fmaf(p, vv.w, acc1[c4 * 4 + 3]);
                            }
                        }
                    }
                }
            }
        }

        // ---- store batch B into nxt buffer
        if (havenext) {
#pragma unroll
            for (int it = 0; it < 4; it++) {
                int r = ld_r + 64 + it * 16;
                int lb = (r >> 3) * 32 + (r & 7) * 4;
                int u = ld_d >> 2;
                nxtb[(lb + 0) * 20 + u] = __uint_as_float(f2tf(pre[it].x));
                nxtb[(lb + 1) * 20 + u] = __uint_as_float(f2tf(pre[it].y));
                nxtb[(lb + 2) * 20 + u] = __uint_as_float(f2tf(pre[it].z));
                nxtb[(lb + 3) * 20 + u] = __uint_as_float(f2tf(pre[it].w));
            }
        }

        // tighten run-min across the quad (converged point, full-mask shfl)
        run0 = fminf(run0, __shfl_xor_sync(0xffffffffu, run0, 1));
        run0 = fminf(run0, __shfl_xor_sync(0xffffffffu, run0, 2));
        run1 = fminf(run1, __shfl_xor_sync(0xffffffffu, run1, 1));
        run1 = fminf(run1, __shfl_xor_sync(0xffffffffu, run1, 2));

        __syncthreads();  // nxt fully written; cur readers done
    }

    // epilogue: normalize and store
    {
        float inv0 = 1.f / rsum0;
        float inv1 = 1.f / rsum1;
        float* o0 = &g_attn[(size_t)R0 * DMODEL + hb + t4 * 16];
        float* o1 = &g_attn[(size_t)R1 * DMODEL + hb + t4 * 16];
#pragma unroll
        for (int c4 = 0; c4 < 4; c4++) {
            float4 a = {acc0[c4 * 4 + 0] * inv0, acc0[c4 * 4 + 1] * inv0,
                        acc0[c4 * 4 + 2] * inv0, acc0[c4 * 4 + 3] * inv0};
            float4 b = {acc1[c4 * 4 + 0] * inv1, acc1[c4 * 4 + 1] * inv1,
                        acc1[c4 * 4 + 2] * inv1, acc1[c4 * 4 + 3] * inv1};
            *(float4*)&o0[c4 * 4] = a;
            *(float4*)&o1[c4 * 4] = b;
        }
    }
}

// ---------------------------------------------------------------------------
// K3: out[4096,64] = g_attn[4096,1024] @ Wm[1024,64] + bm  (R9-verbatim)
// ---------------------------------------------------------------------------
__global__ __launch_bounds__(256) void sgemm_out(
    const float* __restrict__ A, const float* __restrict__ B,
    const float* __restrict__ bias, float* __restrict__ C)
{
    __shared__ float As[16][64];
    __shared__ float Bs[16][64];

    const int tid = threadIdx.x;
    const int tx = tid & 15, ty = tid >> 4;
    const int by = blockIdx.x * 64;

    const int ar = tid >> 2;
    const int ac = (tid & 3) * 4;
    const int br = tid >> 4;
    const int bc = (tid & 15) * 4;

    float acc[4][4];
#pragma unroll
    for (int i = 0; i < 4; i++)
#pragma unroll
        for (int j = 0; j < 4; j++) acc[i][j] = 0.f;

    for (int k0 = 0; k0 < DMODEL; k0 += 16) {
        float4 av = *(const float4*)&A[(size_t)(by + ar) * DMODEL + k0 + ac];
        float4 bv = *(const float4*)&B[(size_t)(k0 + br) * 64 + bc];
        As[ac + 0][ar] = av.x;
        As[ac + 1][ar] = av.y;
        As[ac + 2][ar] = av.z;
        As[ac + 3][ar] = av.w;
        *(float4*)&Bs[br][bc] = bv;
        __syncthreads();
#pragma unroll
        for (int kk = 0; kk < 16; kk++) {
            float4 a = *(const float4*)&As[kk][ty * 4];
            float4 b = *(const float4*)&Bs[kk][tx * 4];
            float av4[4] = {a.x, a.y, a.z, a.w};
            float bv4[4] = {b.x, b.y, b.z, b.w};
#pragma unroll
            for (int i = 0; i < 4; i++)
#pragma unroll
                for (int j = 0; j < 4; j++)
                    acc[i][j] = fmaf(av4[i], bv4[j], acc[i][j]);
        }
        __syncthreads();
    }

#pragma unroll
    for (int i = 0; i < 4; i++) {
        int row = by + ty * 4 + i;
        float4 o;
        o.x = acc[i][0] + bias[tx * 4 + 0];
        o.y = acc[i][1] + bias[tx * 4 + 1];
        o.z = acc[i][2] + bias[tx * 4 + 2];
        o.w = acc[i][3] + bias[tx * 4 + 3];
        *(float4*)&C[(size_t)row * 64 + tx * 4] = o;
    }
}

// ---------------------------------------------------------------------------
// kernel_launch
// ---------------------------------------------------------------------------
extern "C" void kernel_launch(void* const* d_in, const int* in_sizes, int n_in,
                              void* d_out, int out_size)
{
    const float* X  = (const float*)d_in[0];
    const float* Wq = (const float*)d_in[2];
    const float* bq = (const float*)d_in[3];
    const float* Wk = (const float*)d_in[4];
    const float* bk = (const float*)d_in[5];
    const float* Wv = (const float*)d_in[6];
    const float* bv = (const float*)d_in[7];
    const float* Wm = (const float*)d_in[8];
    const float* bm = (const float*)d_in[9];
    float* out = (float*)d_out;

    float *qp, *kp, *vp, *ap;
    cudaGetSymbolAddress((void**)&qp, g_q);
    cudaGetSymbolAddress((void**)&kp, g_k);
    cudaGetSymbolAddress((void**)&vp, g_v);
    cudaGetSymbolAddress((void**)&ap, g_attn);

    sgemm_qkv<<<dim3(24, 32), 256>>>(X, Wq, Wk, Wv, bq, bk, bv, qp, kp, vp);

    cudaFuncSetAttribute(attn_kernel,
                         cudaFuncAttributeMaxDynamicSharedMemorySize,
                         ATT_SMEM_BYTES);
    attn_kernel<<<dim3(SQ / 128, NH), 256, ATT_SMEM_BYTES>>>();

    sgemm_out<<<SQ / 64, 256>>>(ap, Wm, bm, out);
}

// round 11
// speedup vs baseline: 1.0788x; 1.0788x over previous
#include <cuda_runtime.h>
#include <math.h>

#define SQ 4096
#define DMODEL 1024
#define NH 16
#define DH 64

typedef unsigned long long ull;

// Scratch (allocation-free rule: __device__ globals)
__device__ float g_q[SQ * DMODEL];
__device__ float g_k[SQ * DMODEL];
__device__ float g_v[SQ * DMODEL];
__device__ float g_attn[SQ * DMODEL];

// ---------------------------------------------------------------------------
// Packed fp32x2 helpers ("l" = b64 integer carrier)
// ---------------------------------------------------------------------------
__device__ __forceinline__ ull ffma2(ull a, ull b, ull c) {
    ull r;
    asm("fma.rn.f32x2 %0, %1, %2, %3;" : "=l"(r) : "l"(a), "l"(b), "l"(c));
    return r;
}
__device__ __forceinline__ ull pack2(float x) {
    ull r;
    asm("mov.b64 %0, {%1, %1};" : "=l"(r) : "f"(x));
    return r;
}
__device__ __forceinline__ void unpack2(ull d, float& lo, float& hi) {
    asm("mov.b64 {%0, %1}, %2;" : "=f"(lo), "=f"(hi) : "l"(d));
}

// bf16 helpers for the attention filter
// bf2(lo, hi): pack {lo -> bits[15:0], hi -> bits[31:16]} (cvt first src = hi)
__device__ __forceinline__ unsigned bf2(float lo, float hi) {
    unsigned r;
    asm("cvt.rn.bf16x2.f32 %0, %1, %2;" : "=r"(r) : "f"(hi), "f"(lo));
    return r;
}
__device__ __forceinline__ void mma_bf16(
    float& c0, float& c1, float& c2, float& c3,
    unsigned a0, unsigned a1, unsigned a2, unsigned a3,
    unsigned b0, unsigned b1)
{
    asm volatile(
        "mma.sync.aligned.m16n8k16.row.col.f32.bf16.bf16.f32 "
        "{%0,%1,%2,%3}, {%4,%5,%6,%7}, {%8,%9}, {%0,%1,%2,%3};"
        : "+f"(c0), "+f"(c1), "+f"(c2), "+f"(c3)
        : "r"(a0), "r"(a1), "r"(a2), "r"(a3), "r"(b0), "r"(b1));
}

// ---------------------------------------------------------------------------
// K1: FUSED QKV SGEMM (R8/R9-verbatim, known good: ~555-575us)
// ---------------------------------------------------------------------------
__global__ __launch_bounds__(256, 2) void sgemm_qkv(
    const float* __restrict__ A,
    const float* __restrict__ Wq, const float* __restrict__ Wk,
    const float* __restrict__ Wv,
    const float* __restrict__ bq, const float* __restrict__ bk,
    const float* __restrict__ bv,
    float* __restrict__ Cq, float* __restrict__ Ck, float* __restrict__ Cv)
{
    const int which = blockIdx.x >> 3;
    const float* __restrict__ B = (which == 0) ? Wq : (which == 1) ? Wk : Wv;
    const float* __restrict__ bias = (which == 0) ? bq : (which == 1) ? bk : bv;
    float* __restrict__ C = (which == 0) ? Cq : (which == 1) ? Ck : Cv;

    __shared__ float As[8][128];
    __shared__ float Bs[8][128];

    const int tid = threadIdx.x;
    const int tx = tid & 15, ty = tid >> 4;
    const int bx = (blockIdx.x & 7) * 128, by = blockIdx.y * 128;

    const int ar = tid >> 1;
    const int ac = (tid & 1) * 4;
    const int br = tid >> 5;
    const int bc = (tid & 31) * 4;

    ull acc2[8][4];
#pragma unroll
    for (int i = 0; i < 8; i++)
#pragma unroll
        for (int j = 0; j < 4; j++) acc2[i][j] = pack2(0.f);

    const float* Aptr = A + (size_t)(by + ar) * DMODEL + ac;
    const float* Bptr = B + (size_t)br * DMODEL + bx + bc;

    float4 av = *(const float4*)(Aptr);
    float4 bv4 = *(const float4*)(Bptr);

    for (int k0 = 0; k0 < DMODEL; k0 += 8) {
        As[ac + 0][ar] = av.x;
        As[ac + 1][ar] = av.y;
        As[ac + 2][ar] = av.z;
        As[ac + 3][ar] = av.w;
        *(float4*)&Bs[br][bc] = bv4;
        __syncthreads();

        if (k0 + 8 < DMODEL) {
            av = *(const float4*)(Aptr + k0 + 8);
            bv4 = *(const float4*)(Bptr + (size_t)(k0 + 8) * DMODEL);
        }

#pragma unroll
        for (int kk = 0; kk < 8; kk++) {
            ulonglong2 bA = *(const ulonglong2*)&Bs[kk][4 * tx];
            ulonglong2 bB = *(const ulonglong2*)&Bs[kk][64 + 4 * tx];
            float4 a0 = *(const float4*)&As[kk][ty * 8];
            float4 a1 = *(const float4*)&As[kk][ty * 8 + 4];
            float aa[8] = {a0.x, a0.y, a0.z, a0.w, a1.x, a1.y, a1.z, a1.w};
#pragma unroll
            for (int i = 0; i < 8; i++) {
                ull a2 = pack2(aa[i]);
                acc2[i][0] = ffma2(a2, bA.x, acc2[i][0]);
                acc2[i][1] = ffma2(a2, bA.y, acc2[i][1]);
                acc2[i][2] = ffma2(a2, bB.x, acc2[i][2]);
                acc2[i][3] = ffma2(a2, bB.y, acc2[i][3]);
            }
        }
        __syncthreads();
    }

    const int colA = bx + 4 * tx;
    const int colB = colA + 64;
    float4 biasA = *(const float4*)&bias[colA];
    float4 biasB = *(const float4*)&bias[colB];
#pragma unroll
    for (int i = 0; i < 8; i++) {
        int row = by + ty * 8 + i;
        float x0, x1, x2, x3;
        unpack2(acc2[i][0], x0, x1);
        unpack2(acc2[i][1], x2, x3);
        float4 oA = {x0 + biasA.x, x1 + biasA.y, x2 + biasA.z, x3 + biasA.w};
        unpack2(acc2[i][2], x0, x1);
        unpack2(acc2[i][3], x2, x3);
        float4 oB = {x0 + biasB.x, x1 + biasB.y, x2 + biasB.z, x3 + biasB.w};
        *(float4*)&C[(size_t)row * DMODEL + colA] = oA;
        *(float4*)&C[(size_t)row * DMODEL + colB] = oB;
    }
}

// ---------------------------------------------------------------------------
// K2: attention = bf16 TENSOR-CORE FILTER (m16n8k16) + EXACT FP32 RESCUE.
// R9 skeleton (single-buffer, proven); only the filter dtype/shape changed:
// half the MMA instructions, half the K-tile smem/fill/LDS vs tf32 m16n8k8.
//
// Exactness (same superset argument as R9, re-derived for bf16): filter
// error per entry e = sum(dq*k + q*dk), sigma ~ sqrt(128)*1.1e-3 ~ 0.013;
// max over 2.7e8 comparisons ~ 5.8 sigma ~ 0.073; requirement is
// MARGIN >= 2*e_max ~ 0.15; MARGIN = 0.5 gives >3x slack. Rescued entries
// are recomputed exactly in fp32, so the final softmax/V math is bit-
// identical to R9 (rel_err 0.0).
//
// K tile layout: bf16x2 words, word w = dims (2w, 2w+1) of a key, stored
// word-permuted w' = (w&3)*8 + (w>>2) at pitch 36 words. Lane (g, t4) then
// loads its b-fragments for all 4 k-slices of an 8-key tile as two uint4
// reads at [key(g)][t4*8 .. +7]: u[2s], u[2s+1] are exactly (b0, b1) of
// k-slice s. C-fragment layout identical to m16n8k8 -> downstream gating/
// ballot/rescue code is carried over from R9 unchanged.
// ---------------------------------------------------------------------------
#define MARGIN 0.5f
#define KPITCH_W 36
#define ATT_SMEM_BYTES (128 * 68 * 4)   // Q staging (34816B) > K tile (18432B)

__global__ __launch_bounds__(256, 2) void attn_kernel()
{
    extern __shared__ float smf[];
    unsigned* ksw = (unsigned*)smf;

    const int tid = threadIdx.x;
    const int w = tid >> 5, lane = tid & 31;
    const int g = lane >> 2, t4 = lane & 3;
    const int q0 = blockIdx.x * 128;
    const int hb = blockIdx.y * DH;
    const int R0 = q0 + w * 16 + g;
    const int R1 = R0 + 8;
    const unsigned qmask = 0xFu << (lane & 28);

    // ---- Phase 1: stage Q (fp32) and extract bf16 A-fragments
    for (int it = 0; it < 8; it++) {
        int idx = tid + it * 256;
        int r = idx >> 4, d = (idx & 15) * 4;
        float4 t = *(const float4*)&g_q[(size_t)(q0 + r) * DMODEL + hb + d];
        *(float4*)&smf[r * 68 + d] = t;
    }
    __syncthreads();
    unsigned afr[4][4];
    {
        const float* q0p = &smf[(w * 16 + g) * 68];
        const float* q1p = q0p + 8 * 68;
#pragma unroll
        for (int s = 0; s < 4; s++) {
            int kb = 16 * s + 2 * t4;
            afr[s][0] = bf2(q0p[kb], q0p[kb + 1]);
            afr[s][1] = bf2(q1p[kb], q1p[kb + 1]);
            afr[s][2] = bf2(q0p[kb + 8], q0p[kb + 9]);
            afr[s][3] = bf2(q1p[kb + 8], q1p[kb + 9]);
        }
    }

    float run0 = INFINITY, run1 = INFINITY;       // approx s-min (gating only)
    float rmax0 = -INFINITY, rmax1 = -INFINITY;   // exact-side state
    float rsum0 = 0.f, rsum1 = 0.f;
    float acc0[16], acc1[16];
#pragma unroll
    for (int d = 0; d < 16; d++) { acc0[d] = 0.f; acc1[d] = 0.f; }

    const int A0 = q0 + w * 16;
    for (int k0 = 0; k0 < SQ; k0 += 128) {
        __syncthreads();  // previous tile's readers done (1st iter: afr done)
        // fill K tile: bf16x2, word-permuted
        for (int it = 0; it < 8; it++) {
            int idx = tid + it * 256;
            int r = idx >> 4, d = (idx & 15) * 4;
            float4 t = *(const float4*)&g_k[(size_t)(k0 + r) * DMODEL + hb + d];
            int w0 = d >> 1, w1 = w0 + 1;
            ksw[r * KPITCH_W + ((w0 & 3) * 8 + (w0 >> 2))] = bf2(t.x, t.y);
            ksw[r * KPITCH_W + ((w1 & 3) * 8 + (w1 >> 2))] = bf2(t.z, t.w);
        }
        __syncthreads();

        const bool careful = (k0 <= A0 + 15) && (k0 + 127 >= A0 - 1);

#pragma unroll 1
        for (int t = 0; t < 16; t++) {
            const uint4* kf = (const uint4*)&ksw[(t * 8 + g) * KPITCH_W + t4 * 8];
            uint4 u0 = kf[0];
            uint4 u1 = kf[1];
            float c0 = 0.f, c1 = 0.f, c2 = 0.f, c3 = 0.f;
            mma_bf16(c0, c1, c2, c3,
                     afr[0][0], afr[0][1], afr[0][2], afr[0][3], u0.x, u0.y);
            mma_bf16(c0, c1, c2, c3,
                     afr[1][0], afr[1][1], afr[1][2], afr[1][3], u0.z, u0.w);
            mma_bf16(c0, c1, c2, c3,
                     afr[2][0], afr[2][1], afr[2][2], afr[2][3], u1.x, u1.y);
            mma_bf16(c0, c1, c2, c3,
                     afr[3][0], afr[3][1], afr[3][2], afr[3][3], u1.z, u1.w);

            const int j0 = k0 + 8 * t + 2 * t4;
            if (careful) {
                // exclude band cols from the filter min/candidates
                if (j0 == R0 || j0 == R0 - 1) c0 = INFINITY;
                if (j0 + 1 == R0 || j0 + 1 == R0 - 1) c1 = INFINITY;
                if (j0 == R1 || j0 == R1 - 1) c2 = INFINITY;
                if (j0 + 1 == R1 || j0 + 1 == R1 - 1) c3 = INFINITY;
            }
            float m0 = fminf(c0, c1), m1 = fminf(c2, c3);
            run0 = fminf(run0, m0);
            run1 = fminf(run1, m1);
            bool fl = (m0 <= run0 + MARGIN) || (m1 <= run1 + MARGIN);

            if (__any_sync(0xffffffffu, fl)) {
                unsigned bal[4];
                bal[0] = __ballot_sync(0xffffffffu, c0 <= run0 + MARGIN);
                bal[1] = __ballot_sync(0xffffffffu, c1 <= run0 + MARGIN);
                bal[2] = __ballot_sync(0xffffffffu, c2 <= run1 + MARGIN);
                bal[3] = __ballot_sync(0xffffffffu, c3 <= run1 + MARGIN);
#pragma unroll
                for (int e = 0; e < 4; e++) {
                    unsigned qb = (bal[e] >> (lane & 28)) & 0xFu;
                    const int i = (e >= 2) ? R1 : R0;
                    while (qb) {
                        int b = __ffs((int)qb) - 1;
                        qb &= qb - 1;
                        int j = k0 + 8 * t + 2 * b + (e & 1);
                        // exact fp32 dot, quad-cooperative (16 dims/lane)
                        const float* qg = &g_q[(size_t)i * DMODEL + hb + t4 * 16];
                        const float* kg = &g_k[(size_t)j * DMODEL + hb + t4 * 16];
                        float s = 0.f;
#pragma unroll
                        for (int c4 = 0; c4 < 4; c4++) {
                            float4 qv = *(const float4*)&qg[c4 * 4];
                            float4 kv = *(const float4*)&kg[c4 * 4];
                            s = fmaf(qv.x, kv.x, s);
                            s = fmaf(qv.y, kv.y, s);
                            s = fmaf(qv.z, kv.z, s);
                            s = fmaf(qv.w, kv.w, s);
                        }
                        s += __shfl_xor_sync(qmask, s, 1);
                        s += __shfl_xor_sync(qmask, s, 2);
                        float y = s * 0.125f;
                        if (!(j == i || j == i - 1)) y = y * -1000000000.0f;
                        const float* vg = &g_v[(size_t)j * DMODEL + hb + t4 * 16];
                        if (e < 2) {
                            if (y > rmax0) {
                                float scl = expf(rmax0 - y);
                                rsum0 *= scl;
#pragma unroll
                                for (int d = 0; d < 16; d++) acc0[d] *= scl;
                                rmax0 = y;
                            }
                            float p = expf(y - rmax0);
                            rsum0 += p;
#pragma unroll
                            for (int c4 = 0; c4 < 4; c4++) {
                                float4 vv = *(const float4*)&vg[c4 * 4];
                                acc0[c4 * 4 + 0] = fmaf(p, vv.x, acc0[c4 * 4 + 0]);
                                acc0[c4 * 4 + 1] = fmaf(p, vv.y, acc0[c4 * 4 + 1]);
                                acc0[c4 * 4 + 2] = fmaf(p, vv.z, acc0[c4 * 4 + 2]);
                                acc0[c4 * 4 + 3] = fmaf(p, vv.w, acc0[c4 * 4 + 3]);
                            }
                        } else {
                            if (y > rmax1) {
                                float scl = expf(rmax1 - y);
                                rsum1 *= scl;
#pragma unroll
                                for (int d = 0; d < 16; d++) acc1[d] *= scl;
                                rmax1 = y;
                            }
                            float p = expf(y - rmax1);
                            rsum1 += p;
#pragma unroll
                            for (int c4 = 0; c4 < 4; c4++) {
                                float4 vv = *(const float4*)&vg[c4 * 4];
                                acc1[c4 * 4 + 0] = fmaf(p, vv.x, acc1[c4 * 4 + 0]);
                                acc1[c4 * 4 + 1] = fmaf(p, vv.y, acc1[c4 * 4 + 1]);
                                acc1[c4 * 4 + 2] = fmaf(p, vv.z, acc1[c4 * 4 + 2]);
                                acc1[c4 * 4 + 3] = fmaf(p, vv.w, acc1[c4 * 4 + 3]);
                            }
                        }
                    }
                }
            }
        }
        // tighten run-min across the quad (converged point, full-mask shfl)
        run0 = fminf(run0, __shfl_xor_sync(0xffffffffu, run0, 1));
        run0 = fminf(run0, __shfl_xor_sync(0xffffffffu, run0, 2));
        run1 = fminf(run1, __shfl_xor_sync(0xffffffffu, run1, 1));
        run1 = fminf(run1, __shfl_xor_sync(0xffffffffu, run1, 2));
    }

    // epilogue: normalize and store
    {
        float inv0 = 1.f / rsum0;
        float inv1 = 1.f / rsum1;
        float* o0 = &g_attn[(size_t)R0 * DMODEL + hb + t4 * 16];
        float* o1 = &g_attn[(size_t)R1 * DMODEL + hb + t4 * 16];
#pragma unroll
        for (int c4 = 0; c4 < 4; c4++) {
            float4 a = {acc0[c4 * 4 + 0] * inv0, acc0[c4 * 4 + 1] * inv0,
                        acc0[c4 * 4 + 2] * inv0, acc0[c4 * 4 + 3] * inv0};
            float4 b = {acc1[c4 * 4 + 0] * inv1, acc1[c4 * 4 + 1] * inv1,
                        acc1[c4 * 4 + 2] * inv1, acc1[c4 * 4 + 3] * inv1};
            *(float4*)&o0[c4 * 4] = a;
            *(float4*)&o1[c4 * 4] = b;
        }
    }
}

// ---------------------------------------------------------------------------
// K3: out[4096,64] = g_attn[4096,1024] @ Wm[1024,64] + bm  (verbatim)
// ---------------------------------------------------------------------------
__global__ __launch_bounds__(256) void sgemm_out(
    const float* __restrict__ A, const float* __restrict__ B,
    const float* __restrict__ bias, float* __restrict__ C)
{
    __shared__ float As[16][64];
    __shared__ float Bs[16][64];

    const int tid = threadIdx.x;
    const int tx = tid & 15, ty = tid >> 4;
    const int by = blockIdx.x * 64;

    const int ar = tid >> 2;
    const int ac = (tid & 3) * 4;
    const int br = tid >> 4;
    const int bc = (tid & 15) * 4;

    float acc[4][4];
#pragma unroll
    for (int i = 0; i < 4; i++)
#pragma unroll
        for (int j = 0; j < 4; j++) acc[i][j] = 0.f;

    for (int k0 = 0; k0 < DMODEL; k0 += 16) {
        float4 av = *(const float4*)&A[(size_t)(by + ar) * DMODEL + k0 + ac];
        float4 bv = *(const float4*)&B[(size_t)(k0 + br) * 64 + bc];
        As[ac + 0][ar] = av.x;
        As[ac + 1][ar] = av.y;
        As[ac + 2][ar] = av.z;
        As[ac + 3][ar] = av.w;
        *(float4*)&Bs[br][bc] = bv;
        __syncthreads();
#pragma unroll
        for (int kk = 0; kk < 16; kk++) {
            float4 a = *(const float4*)&As[kk][ty * 4];
            float4 b = *(const float4*)&Bs[kk][tx * 4];
            float av4[4] = {a.x, a.y, a.z, a.w};
            float bv4[4] = {b.x, b.y, b.z, b.w};
#pragma unroll
            for (int i = 0; i < 4; i++)
#pragma unroll
                for (int j = 0; j < 4; j++)
                    acc[i][j] = fmaf(av4[i], bv4[j], acc[i][j]);
        }
        __syncthreads();
    }

#pragma unroll
    for (int i = 0; i < 4; i++) {
        int row = by + ty * 4 + i;
        float4 o;
        o.x = acc[i][0] + bias[tx * 4 + 0];
        o.y = acc[i][1] + bias[tx * 4 + 1];
        o.z = acc[i][2] + bias[tx * 4 + 2];
        o.w = acc[i][3] + bias[tx * 4 + 3];
        *(float4*)&C[(size_t)row * 64 + tx * 4] = o;
    }
}

// ---------------------------------------------------------------------------
// kernel_launch
// ---------------------------------------------------------------------------
extern "C" void kernel_launch(void* const* d_in, const int* in_sizes, int n_in,
                              void* d_out, int out_size)
{
    const float* X  = (const float*)d_in[0];
    const float* Wq = (const float*)d_in[2];
    const float* bq = (const float*)d_in[3];
    const float* Wk = (const float*)d_in[4];
    const float* bk = (const float*)d_in[5];
    const float* Wv = (const float*)d_in[6];
    const float* bv = (const float*)d_in[7];
    const float* Wm = (const float*)d_in[8];
    const float* bm = (const float*)d_in[9];
    float* out = (float*)d_out;

    float *qp, *kp, *vp, *ap;
    cudaGetSymbolAddress((void**)&qp, g_q);
    cudaGetSymbolAddress((void**)&kp, g_k);
    cudaGetSymbolAddress((void**)&vp, g_v);
    cudaGetSymbolAddress((void**)&ap, g_attn);

    sgemm_qkv<<<dim3(24, 32), 256>>>(X, Wq, Wk, Wv, bq, bk, bv, qp, kp, vp);

    cudaFuncSetAttribute(attn_kernel,
                         cudaFuncAttributeMaxDynamicSharedMemorySize,
                         ATT_SMEM_BYTES);
    attn_kernel<<<dim3(SQ / 128, NH), 256, ATT_SMEM_BYTES>>>();

    sgemm_out<<<SQ / 64, 256>>>(ap, Wm, bm, out);
}